// round 16
// baseline (speedup 1.0000x reference)
#include <cuda_runtime.h>
#include <cuda_bf16.h>
#include <cuda_fp16.h>
#include <stdint.h>

#define BB   32
#define TT   20
#define HH   100
#define GG   300      // 3H
#define DD   200      // 2H
#define KK   200      // GEMM K
#define VV   32000

// ---------------- scratch (static device globals; no allocation) ----------------
__device__ float g_y0  [BB*TT*DD];
__device__ float g_gx1 [BB*TT*2*GG];   // combined fwd|bwd, row stride 600
__device__ float g_y1  [BB*TT*DD];
// fp16 weights: W_lin | W_ih_l1f | W_ih_l1b
#define WL_OFF  0
#define W1F_OFF (VV*KK)
#define W1B_OFF (VV*KK + GG*KK)
#define W16_N4  ((VV*KK + 2*GG*KK)/4)
__device__ __half g_w16[VV*KK + 2*GG*KK];

// ================= helpers =================
__device__ __forceinline__ uint32_t smem_u32(const void* p) {
    uint32_t a;
    asm("{ .reg .u64 t; cvta.to.shared.u64 t, %1; cvt.u32.u64 %0, t; }" : "=r"(a) : "l"(p));
    return a;
}
__device__ __forceinline__ void ldsm4(uint32_t* r, uint32_t addr) {
    asm volatile("ldmatrix.sync.aligned.m8n8.x4.shared.b16 {%0,%1,%2,%3}, [%4];"
        : "=r"(r[0]), "=r"(r[1]), "=r"(r[2]), "=r"(r[3]) : "r"(addr));
}
__device__ __forceinline__ void mma_fp16(float* c, const uint32_t* a,
                                         uint32_t b0, uint32_t b1) {
    asm volatile("mma.sync.aligned.m16n8k16.row.col.f32.f16.f16.f32 "
        "{%0,%1,%2,%3}, {%4,%5,%6,%7}, {%8,%9}, {%0,%1,%2,%3};"
        : "+f"(c[0]), "+f"(c[1]), "+f"(c[2]), "+f"(c[3])
        : "r"(a[0]), "r"(a[1]), "r"(a[2]), "r"(a[3]), "r"(b0), "r"(b1));
}
__device__ __forceinline__ uint32_t cvt2_fp(float a, float b) {
    __half2 h2 = __floats2half2_rn(a, b);
    return *reinterpret_cast<uint32_t*>(&h2);
}
__device__ __forceinline__ unsigned long long pack_f32x2(float lo, float hi) {
    unsigned long long r;
    asm("mov.b64 %0, {%1, %2};" : "=l"(r) : "f"(lo), "f"(hi));
    return r;
}
__device__ __forceinline__ unsigned long long fma_f32x2(
    unsigned long long a, unsigned long long b, unsigned long long c) {
    unsigned long long d;
    asm("fma.rn.f32x2 %0, %1, %2, %3;" : "=l"(d) : "l"(a), "l"(b), "l"(c));
    return d;
}
__device__ __forceinline__ void unpack_f32x2(unsigned long long v, float& lo, float& hi) {
    asm("mov.b64 {%0, %1}, %2;" : "=f"(lo), "=f"(hi) : "l"(v));
}
__device__ __forceinline__ float tanh_f(float x) {
    float y;
    asm("tanh.approx.f32 %0, %1;" : "=f"(y) : "f"(x));
    return y;
}
#define STS32(addr, v) \
    asm volatile("st.shared.b32 [%0], %1;" :: "r"(addr), "r"(v) : "memory")
#define CP_ASYNC16(saddr, gaddr) \
    asm volatile("cp.async.cg.shared.global [%0], [%1], 16;" \
        :: "r"(saddr), "l"(gaddr) : "memory")
#define CP_COMMIT() asm volatile("cp.async.commit_group;" ::: "memory")
#define CP_WAIT1()  asm volatile("cp.async.wait_group 1;"  ::: "memory")
#define CP_WAIT0()  asm volatile("cp.async.wait_group 0;"  ::: "memory")

#define GRU_THR 320

// ---------------- GRU core: 3 lanes per unit, full dots, 1 barrier/step -----
// 320 threads = 10 warps; warp w owns units 10w..10w+9. Lane = 3i+g (g=gate),
// lanes 30,31 idle. Each lane holds the FULL 100-wide W row in 50 f32x2 regs
// and computes the whole dot (no pair reduce). shfl_down(1)/(2) bring the z,n
// dots to the r-lane, which does the whole activation. h double-buffered.
__device__ __forceinline__ void gru_core(
    float* gx_all, float (*h_s)[104], const float* Whh,
    const float* hidden, int hid_base, int dir, int b,
    float* y, float* hout, int tid)
{
    const int wid  = tid >> 5, lane = tid & 31;
    int i = lane / 3; if (i > 9) i = 9;        // clamp idle lanes 30,31
    const int g = lane - i*3 > 2 ? 2 : lane - i*3;
    const int u = wid * 10 + i;
    const bool store_lane = (lane % 3 == 0) && (lane < 30);

    // full weight row for (gate g, unit u): 100 floats -> 50 f32x2
    unsigned long long w2[50];
    {
        const float* wrow = Whh + (g*HH + u)*HH;
        #pragma unroll
        for (int k = 0; k < 50; k++)
            w2[k] = pack_f32x2(wrow[2*k], wrow[2*k+1]);
    }

    if (tid < HH) h_s[0][tid] = hidden[(hid_base + dir)*BB*HH + b*HH + tid];
    if (tid < 8) { h_s[0][100 + (tid&3)] = 0.f; h_s[1][100 + (tid&3)] = 0.f; }
    __syncthreads();

    const uint32_t hbase0 = smem_u32(&h_s[0][0]);
    const uint32_t hbase1 = smem_u32(&h_s[1][0]);

    for (int t = 0; t < TT; t++) {
        int tt = dir ? (TT-1-t) : t;
        const float* gxr = gx_all + tt*GG;
        const int cur = t & 1;
        const uint32_t hb = cur ? hbase1 : hbase0;

        float xr = gxr[u], xz = gxr[HH+u], xn = gxr[2*HH+u];
        float ho = h_s[cur][u];

        // 25 x 16B broadcast loads, 2 packed FMAs each (2 indep chains of 25)
        unsigned long long acc0 = 0ull, acc1 = 0ull;
        unsigned long long p0, q0, p1, q1;
        asm volatile("ld.shared.v2.u64 {%0,%1}, [%2];" : "=l"(p0), "=l"(q0) : "r"(hb));
        #pragma unroll
        for (int kk = 0; kk < 25; kk++) {
            if (kk < 24) {
                asm volatile("ld.shared.v2.u64 {%0,%1}, [%2];"
                    : "=l"(p1), "=l"(q1) : "r"(hb + (uint32_t)(kk+1)*16));
            }
            acc0 = fma_f32x2(w2[2*kk],   p0, acc0);
            acc1 = fma_f32x2(w2[2*kk+1], q0, acc1);
            p0 = p1; q0 = q1;
        }
        float a0, a1, a2, a3;
        unpack_f32x2(acc0, a0, a1);
        unpack_f32x2(acc1, a2, a3);
        float dot = (a0 + a1) + (a2 + a3);

        // gate exchange within aligned triplet: r-lane gets z (d+1), n (d+2)
        float hz = __shfl_down_sync(0xffffffffu, dot, 1);
        float hn = __shfl_down_sync(0xffffffffu, dot, 2);

        float r  = fmaf(tanh_f(0.5f*(xr + dot)), 0.5f, 0.5f);
        float z  = fmaf(tanh_f(0.5f*(xz + hz)),  0.5f, 0.5f);
        float uu = xn + r*hn;
        float nn = tanh_f(uu);
        float hv = (1.f - z)*nn + z*ho;
        if (store_lane) {
            h_s[cur ^ 1][u] = hv;
            y[(b*TT + tt)*DD + dir*HH + u] = hv;
        }
        __syncthreads();
    }
    if (tid < HH) hout[(hid_base + dir)*BB*HH + b*HH + tid] = h_s[0][tid];
}

// ---------------- layer-0 GRU: fused embedding gather + weight convert ------
__global__ __launch_bounds__(GRU_THR) void gru0_fused(
    const int* __restrict__ x,
    const float* __restrict__ Wih0f, const float* __restrict__ Wih0b,
    const float* __restrict__ Whh0f, const float* __restrict__ Whh0b,
    const float* __restrict__ hidden,
    float* __restrict__ y, float* __restrict__ hout,
    const float* __restrict__ Wlin,
    const float* __restrict__ W1f, const float* __restrict__ W1b)
{
    const int tid = threadIdx.x;
    if (blockIdx.x >= 64) {
        const int cb = blockIdx.x - 64;              // 0..83
        const int stride = 84 * GRU_THR;
        for (int e4 = cb*GRU_THR + tid; e4 < W16_N4; e4 += stride) {
            const float* src;
            int off4;
            if (e4 < VV*KK/4)                 { src = Wlin; off4 = e4; }
            else if (e4 < (VV*KK + GG*KK)/4)  { src = W1f;  off4 = e4 - VV*KK/4; }
            else                              { src = W1b;  off4 = e4 - (VV*KK + GG*KK)/4; }
            float4 v = *reinterpret_cast<const float4*>(src + off4*4);
            __half2* o = reinterpret_cast<__half2*>(g_w16 + (size_t)e4*4);
            o[0] = __floats2half2_rn(v.x, v.y);
            o[1] = __floats2half2_rn(v.z, v.w);
        }
        return;
    }

    int dir = blockIdx.x >> 5;
    int b   = blockIdx.x & 31;
    const float* Wih = dir ? Wih0b : Wih0f;
    const float* Whh = dir ? Whh0b : Whh0f;

    __shared__ __align__(16) float h_s[2][104];
    __shared__ __align__(16) float gx_all[TT*GG + 8];
    __shared__ int tok_s[TT];

    if (tid < TT) tok_s[tid] = x[b*TT + tid];
    __syncthreads();

    for (int q = tid; q < TT*GG; q += GRU_THR) {
        int row = q / GG, gg = q - row*GG;
        gx_all[q] = Wih[(size_t)gg*VV + tok_s[row]];
    }

    gru_core(gx_all, h_s, Whh, hidden, 0, dir, b, y, hout, tid);
}

// ---------------- layer-1 GRU ----------------
__global__ __launch_bounds__(GRU_THR) void gru1_kernel(
    const float* __restrict__ gxf, const float* __restrict__ gxb, int ldg_,
    const float* __restrict__ Whhf, const float* __restrict__ Whhb,
    const float* __restrict__ hidden,
    float* __restrict__ y, float* __restrict__ hout)
{
    int dir = blockIdx.x >> 5;
    int b   = blockIdx.x & 31;
    const float* gx  = dir ? gxb  : gxf;
    const float* Whh = dir ? Whhb : Whhf;
    const int tid = threadIdx.x;

    __shared__ __align__(16) float h_s[2][104];
    __shared__ __align__(16) float gx_all[TT*GG + 8];

    for (int q = tid; q < TT*(GG/2); q += GRU_THR) {
        int row = q / (GG/2);
        int c2  = q - row*(GG/2);
        *reinterpret_cast<float2*>(gx_all + row*GG + c2*2) =
            *reinterpret_cast<const float2*>(gx + (size_t)(b*TT + row)*ldg_ + c2*2);
    }

    gru_core(gx_all, h_s, Whh, hidden, 2, dir, b, y, hout, tid);
}

// ================= shared GEMM constants =====================================
#define KP   216
#define KC   13
#define A_BY 55296

// ================= projection GEMM: fp16 1-pass, cp.async, 1 tile/CTA ========
#define PJ_SMEM 110592    // A + B

__global__ __launch_bounds__(512, 1) void pj_gemm(
    const float* __restrict__ A, const __half* __restrict__ Bw,
    float* __restrict__ C)
{
    const int Ntot = 2*GG;   // 600
    extern __shared__ __align__(16) unsigned char dsm[];
    const uint32_t sb = smem_u32(dsm);
    const int tid = threadIdx.x;
    const int m0  = blockIdx.x * 128;
    const int n0  = blockIdx.y * 128;

    // zero K pads of both regions (A, B)
    for (int q = tid; q < 2*1024; q += 512) {
        int reg = q >> 10;
        int j   = q & 1023;
        int row = j >> 3, wd = j & 7;
        STS32(sb + (uint32_t)reg*A_BY + ((uint32_t)row*KP + 200)*2 + (uint32_t)wd*4, 0u);
    }

    // cp.async B tile (row-guarded)
    #pragma unroll
    for (int q = 0; q < 7; q++) {
        int u = tid + q*512;
        if (u < 3200) {
            int row = u / 25, ch = u % 25;
            int gr  = n0 + row;
            if (gr < Ntot)
                CP_ASYNC16(sb + A_BY + (uint32_t)row*(KP*2) + (uint32_t)ch*16,
                           (const void*)(Bw + (size_t)gr*KK + ch*8));
        }
    }
    CP_COMMIT();

    // load + convert A
    #pragma unroll
    for (int q = 0; q < 25; q++) {
        int u = tid + q*512;
        int row = u / 100, c2 = u % 100;
        float2 v = *reinterpret_cast<const float2*>(A + (size_t)(m0+row)*KK + c2*2);
        STS32(sb + ((uint32_t)row*KP + (uint32_t)c2*2)*2, cvt2_fp(v.x, v.y));
    }
    CP_WAIT0();
    __syncthreads();

    const int wid = tid >> 5, lane = tid & 31;
    const int wm = wid & 3, wn = wid >> 2;
    const int lr = lane & 7, lq = lane >> 3;
    const uint32_t aRow = (uint32_t)(wm*32 + (lq & 1)*8 + lr);
    const uint32_t aCol = (uint32_t)((lq >> 1)*8);
    const uint32_t bRow = (uint32_t)(wn*32 + (lq >> 1)*8 + lr);
    const uint32_t bCol = (uint32_t)((lq & 1)*8);
    const uint32_t aB = sb + (aRow*KP + aCol)*2;
    const uint32_t bB = sb + A_BY + (bRow*KP + bCol)*2;

    float acc[2][4][4];
    #pragma unroll
    for (int mt = 0; mt < 2; mt++)
        #pragma unroll
        for (int ns = 0; ns < 4; ns++)
            #pragma unroll
            for (int q = 0; q < 4; q++) acc[mt][ns][q] = 0.f;

    #pragma unroll
    for (int kc = 0; kc < KC; kc++) {
        const uint32_t kOff = (uint32_t)kc * 32;
        uint32_t ah[2][4], bh[2][4];
        #pragma unroll
        for (int mt = 0; mt < 2; mt++)
            ldsm4(ah[mt], aB + (uint32_t)(mt*16*KP)*2 + kOff);
        #pragma unroll
        for (int nb = 0; nb < 2; nb++)
            ldsm4(bh[nb], bB + (uint32_t)(nb*16*KP)*2 + kOff);
        #pragma unroll
        for (int mt = 0; mt < 2; mt++)
            #pragma unroll
            for (int ns = 0; ns < 4; ns++)
                mma_fp16(acc[mt][ns], ah[mt],
                         bh[ns>>1][(ns&1)*2], bh[ns>>1][(ns&1)*2+1]);
    }

    const int r0 = m0 + wm*32 + (lane >> 2);
    const int c0 = n0 + wn*32 + (lane & 3)*2;
    #pragma unroll
    for (int mt = 0; mt < 2; mt++)
        #pragma unroll
        for (int ns = 0; ns < 4; ns++) {
            int row = r0 + mt*16;
            int col = c0 + ns*8;
            if (col < Ntot) {
                *reinterpret_cast<float2*>(C + (size_t)row*Ntot + col) =
                    make_float2(acc[mt][ns][0], acc[mt][ns][1]);
                *reinterpret_cast<float2*>(C + (size_t)(row+8)*Ntot + col) =
                    make_float2(acc[mt][ns][2], acc[mt][ns][3]);
            }
        }
}

// ================= final GEMM: fp16, cp.async 3-stage, 128x128 tiles =========
// (Round-12 configuration: best measured — 16 warps, 1 CTA/SM, 3-stage.)
#define WG_SMEM 221184     // A + 3 B stages

__global__ __launch_bounds__(512, 1) void wl_gemm(
    const float* __restrict__ A, const __half* __restrict__ Bw,
    float* __restrict__ C)
{
    extern __shared__ __align__(16) unsigned char dsm[];
    const uint32_t sb = smem_u32(dsm);
    const int tid = threadIdx.x;
    const int m0  = blockIdx.x * 128;
    const int c   = blockIdx.y;
    const int S   = gridDim.y;
    const int ntn = VV / 128;          // 250

    for (int q = tid; q < 4*128*8; q += 512) {
        int reg = q >> 10;
        int j   = q & 1023;
        int row = j >> 3, wd = j & 7;
        STS32(sb + (uint32_t)reg*A_BY + ((uint32_t)row*KP + 200)*2 + (uint32_t)wd*4, 0u);
    }

    #pragma unroll
    for (int q = 0; q < 25; q++) {
        int u = tid + q*512;
        int row = u / 100, c2 = u % 100;
        float2 v = *reinterpret_cast<const float2*>(A + (size_t)(m0+row)*KK + c2*2);
        STS32(sb + ((uint32_t)row*KP + (uint32_t)c2*2)*2, cvt2_fp(v.x, v.y));
    }

    auto issue = [&](int tn, int st) {
        const int n0 = tn * 128;
        const uint32_t bs = sb + (uint32_t)(1 + st)*A_BY;
        #pragma unroll
        for (int q = 0; q < 7; q++) {
            int u = tid + q*512;
            if (u < 3200) {
                int row = u / 25, ch = u % 25;
                const __half* gp = Bw + (size_t)(n0 + row)*KK + ch*8;
                CP_ASYNC16(bs + (uint32_t)row*(KP*2) + (uint32_t)ch*16,
                           (const void*)gp);
            }
        }
    };

    {
        int t0 = c;
        if (t0 < ntn) issue(t0, 0);
        CP_COMMIT();
        int t1 = c + S;
        if (t1 < ntn) issue(t1, 1);
        CP_COMMIT();
    }

    const int wid = tid >> 5, lane = tid & 31;
    const int wm = wid & 3, wn = wid >> 2;
    const int lr = lane & 7, lq = lane >> 3;
    const uint32_t aRow = (uint32_t)(wm*32 + (lq & 1)*8 + lr);
    const uint32_t aCol = (uint32_t)((lq >> 1)*8);
    const uint32_t bRow = (uint32_t)(wn*32 + (lq >> 1)*8 + lr);
    const uint32_t bCol = (uint32_t)((lq & 1)*8);
    const uint32_t aB = sb + (aRow*KP + aCol)*2;
    uint32_t bB[3];
    #pragma unroll
    for (int s2 = 0; s2 < 3; s2++)
        bB[s2] = sb + (uint32_t)(1 + s2)*A_BY + (bRow*KP + bCol)*2;

    int phase = 0;
    for (int t = c; t < ntn; t += S, phase++) {
        const int slot = phase % 3;
        const int n0   = t * 128;

        CP_WAIT1();
        __syncthreads();

        const int tn = t + 2*S;
        if (tn < ntn) issue(tn, (phase + 2) % 3);
        CP_COMMIT();

        float acc[2][4][4];
        #pragma unroll
        for (int mt = 0; mt < 2; mt++)
            #pragma unroll
            for (int ns = 0; ns < 4; ns++)
                #pragma unroll
                for (int q = 0; q < 4; q++) acc[mt][ns][q] = 0.f;

        #pragma unroll
        for (int kc = 0; kc < KC; kc++) {
            const uint32_t kOff = (uint32_t)kc * 32;
            uint32_t ah[2][4], bh[2][4];
            #pragma unroll
            for (int mt = 0; mt < 2; mt++)
                ldsm4(ah[mt], aB + (uint32_t)(mt*16*KP)*2 + kOff);
            #pragma unroll
            for (int nb = 0; nb < 2; nb++)
                ldsm4(bh[nb], bB[slot] + (uint32_t)(nb*16*KP)*2 + kOff);
            #pragma unroll
            for (int mt = 0; mt < 2; mt++)
                #pragma unroll
                for (int ns = 0; ns < 4; ns++)
                    mma_fp16(acc[mt][ns], ah[mt], bh[ns>>1][(ns&1)*2], bh[ns>>1][(ns&1)*2+1]);
        }

        const int r0 = m0 + wm*32 + (lane >> 2);
        const int c0 = n0 + wn*32 + (lane & 3)*2;
        #pragma unroll
        for (int mt = 0; mt < 2; mt++)
            #pragma unroll
            for (int ns = 0; ns < 4; ns++) {
                int row = r0 + mt*16;
                int col = c0 + ns*8;
                *reinterpret_cast<float2*>(C + (size_t)row*VV + col) =
                    make_float2(acc[mt][ns][0], acc[mt][ns][1]);
                *reinterpret_cast<float2*>(C + (size_t)(row+8)*VV + col) =
                    make_float2(acc[mt][ns][2], acc[mt][ns][3]);
            }
    }
}

// ---------------- launch ----------------
extern "C" void kernel_launch(void* const* d_in, const int* in_sizes, int n_in,
                              void* d_out, int out_size) {
    const int*   x      = (const int*)  d_in[0];
    const float* hidden = (const float*)d_in[1];
    const float* Wih0f  = (const float*)d_in[2];
    const float* Whh0f  = (const float*)d_in[3];
    const float* Wih0b  = (const float*)d_in[4];
    const float* Whh0b  = (const float*)d_in[5];
    const float* Wih1f  = (const float*)d_in[6];
    const float* Whh1f  = (const float*)d_in[7];
    const float* Wih1b  = (const float*)d_in[8];
    const float* Whh1b  = (const float*)d_in[9];
    const float* Wlin   = (const float*)d_in[10];

    float* out  = (float*)d_out;
    float* hout = out + (out_size - 4*BB*HH);

    void *p_y0, *p_gx1, *p_y1, *p_w16;
    cudaGetSymbolAddress(&p_y0,   g_y0);
    cudaGetSymbolAddress(&p_gx1,  g_gx1);
    cudaGetSymbolAddress(&p_y1,   g_y1);
    cudaGetSymbolAddress(&p_w16,  g_w16);
    __half* w16 = (__half*)p_w16;

    cudaFuncSetAttribute(pj_gemm, cudaFuncAttributeMaxDynamicSharedMemorySize, PJ_SMEM);
    cudaFuncSetAttribute(wl_gemm, cudaFuncAttributeMaxDynamicSharedMemorySize, WG_SMEM);

    // 1. GRU layer 0 (fused gather + fp16 converts on idle SMs)
    gru0_fused<<<148, GRU_THR>>>(x, Wih0f, Wih0b, Whh0f, Whh0b, hidden,
                                 (float*)p_y0, hout, Wlin, Wih1f, Wih1b);

    // 2. fused layer-1 projections (fp16 1-pass, grid 5x5)
    pj_gemm<<<dim3(5, 5), 512, PJ_SMEM>>>((const float*)p_y0,
                                          w16 + W1F_OFF, (float*)p_gx1);

    // 3. GRU layer 1
    gru1_kernel<<<64, GRU_THR>>>((const float*)p_gx1, (const float*)p_gx1 + GG,
                                 2*GG, Whh1f, Whh1b, hidden,
                                 (float*)p_y1, hout);

    // 4. final projection: fp16 cp.async 3-stage, grid 5x29 (round-12 config)
    wl_gemm<<<dim3(5, 29), 512, WG_SMEM>>>((const float*)p_y1,
                                           w16 + WL_OFF, out);
}

// round 17
// speedup vs baseline: 1.0850x; 1.0850x over previous
#include <cuda_runtime.h>
#include <cuda_bf16.h>
#include <cuda_fp16.h>
#include <stdint.h>

#define BB   32
#define TT   20
#define HH   100
#define GG   300      // 3H
#define DD   200      // 2H
#define KK   200      // GEMM K
#define VV   32000

// ---------------- scratch (static device globals; no allocation) ----------------
__device__ float g_y0  [BB*TT*DD];
__device__ float g_gx1 [BB*TT*2*GG];   // combined fwd|bwd, row stride 600
__device__ float g_y1  [BB*TT*DD];
// fp16 weights: W_lin | W_ih_l1f | W_ih_l1b
#define WL_OFF  0
#define W1F_OFF (VV*KK)
#define W1B_OFF (VV*KK + GG*KK)
#define W16_N4  ((VV*KK + 2*GG*KK)/4)
__device__ __half g_w16[VV*KK + 2*GG*KK];

// ================= helpers =================
__device__ __forceinline__ uint32_t smem_u32(const void* p) {
    uint32_t a;
    asm("{ .reg .u64 t; cvta.to.shared.u64 t, %1; cvt.u32.u64 %0, t; }" : "=r"(a) : "l"(p));
    return a;
}
__device__ __forceinline__ void ldsm4(uint32_t* r, uint32_t addr) {
    asm volatile("ldmatrix.sync.aligned.m8n8.x4.shared.b16 {%0,%1,%2,%3}, [%4];"
        : "=r"(r[0]), "=r"(r[1]), "=r"(r[2]), "=r"(r[3]) : "r"(addr));
}
__device__ __forceinline__ void mma_fp16(float* c, const uint32_t* a,
                                         uint32_t b0, uint32_t b1) {
    asm volatile("mma.sync.aligned.m16n8k16.row.col.f32.f16.f16.f32 "
        "{%0,%1,%2,%3}, {%4,%5,%6,%7}, {%8,%9}, {%0,%1,%2,%3};"
        : "+f"(c[0]), "+f"(c[1]), "+f"(c[2]), "+f"(c[3])
        : "r"(a[0]), "r"(a[1]), "r"(a[2]), "r"(a[3]), "r"(b0), "r"(b1));
}
__device__ __forceinline__ uint32_t cvt2_fp(float a, float b) {
    __half2 h2 = __floats2half2_rn(a, b);
    return *reinterpret_cast<uint32_t*>(&h2);
}
__device__ __forceinline__ unsigned long long pack_f32x2(float lo, float hi) {
    unsigned long long r;
    asm("mov.b64 %0, {%1, %2};" : "=l"(r) : "f"(lo), "f"(hi));
    return r;
}
__device__ __forceinline__ unsigned long long fma_f32x2(
    unsigned long long a, unsigned long long b, unsigned long long c) {
    unsigned long long d;
    asm("fma.rn.f32x2 %0, %1, %2, %3;" : "=l"(d) : "l"(a), "l"(b), "l"(c));
    return d;
}
__device__ __forceinline__ void unpack_f32x2(unsigned long long v, float& lo, float& hi) {
    asm("mov.b64 {%0, %1}, %2;" : "=f"(lo), "=f"(hi) : "l"(v));
}
__device__ __forceinline__ float tanh_f(float x) {
    float y;
    asm("tanh.approx.f32 %0, %1;" : "=f"(y) : "f"(x));
    return y;
}
#define STS32(addr, v) \
    asm volatile("st.shared.b32 [%0], %1;" :: "r"(addr), "r"(v) : "memory")
#define CP_ASYNC16(saddr, gaddr) \
    asm volatile("cp.async.cg.shared.global [%0], [%1], 16;" \
        :: "r"(saddr), "l"(gaddr) : "memory")
#define CP_COMMIT() asm volatile("cp.async.commit_group;" ::: "memory")
#define CP_WAIT1()  asm volatile("cp.async.wait_group 1;"  ::: "memory")
#define CP_WAIT0()  asm volatile("cp.async.wait_group 0;"  ::: "memory")

// ---------------- GRU recurrence core (round-15 config: 640 thr) ------------
__device__ __forceinline__ void gru_core(
    float* gx_all, float (*h_s)[104], const float* Whh,
    const float* hidden, int hid_base, int dir, int b,
    float* y, float* hout, int tid)
{
    int wid  = tid >> 5, lane = tid & 31;
    int i    = lane / 6;  if (i > 4) i = 4;
    int rr   = lane % 6;
    int g    = rr >> 1;
    int s    = rr & 1;
    int u    = wid * 5 + i;
    bool store_lane = (lane % 6 == 0) && (lane < 30);

    const int base = s * 52;
    const int wcnt = s ? 48 : 52;
    unsigned long long w2[26];
    {
        const float* wrow = Whh + (g*HH + u)*HH + base;
        #pragma unroll
        for (int k = 0; k < 26; k++) {
            float wa = (2*k   < wcnt) ? wrow[2*k]   : 0.f;
            float wb = (2*k+1 < wcnt) ? wrow[2*k+1] : 0.f;
            w2[k] = pack_f32x2(wa, wb);
        }
    }

    if (tid < HH) h_s[0][tid] = hidden[(hid_base + dir)*BB*HH + b*HH + tid];
    if (tid < 8) { h_s[0][100 + (tid&3)] = 0.f; h_s[1][100 + (tid&3)] = 0.f; }
    __syncthreads();

    const uint32_t hbase0 = smem_u32(&h_s[0][0]) + (uint32_t)base*4;
    const uint32_t hbase1 = smem_u32(&h_s[1][0]) + (uint32_t)base*4;

    for (int t = 0; t < TT; t++) {
        int tt = dir ? (TT-1-t) : t;
        const float* gxr = gx_all + tt*GG;
        const int cur = t & 1;
        const uint32_t hb = cur ? hbase1 : hbase0;

        float xr = gxr[u], xz = gxr[HH+u], xn = gxr[2*HH+u];
        float ho = h_s[cur][u];

        unsigned long long acc0 = 0ull, acc1 = 0ull;
        unsigned long long p0, q0, p1, q1;
        asm volatile("ld.shared.v2.u64 {%0,%1}, [%2];" : "=l"(p0), "=l"(q0) : "r"(hb));
        #pragma unroll
        for (int kk = 0; kk < 13; kk++) {
            if (kk < 12) {
                asm volatile("ld.shared.v2.u64 {%0,%1}, [%2];"
                    : "=l"(p1), "=l"(q1) : "r"(hb + (uint32_t)(kk+1)*16));
            }
            acc0 = fma_f32x2(w2[2*kk],   p0, acc0);
            acc1 = fma_f32x2(w2[2*kk+1], q0, acc1);
            p0 = p1; q0 = q1;
        }
        float a0, a1, a2, a3;
        unpack_f32x2(acc0, a0, a1);
        unpack_f32x2(acc1, a2, a3);
        float dot = (a0 + a1) + (a2 + a3);
        dot += __shfl_xor_sync(0xffffffffu, dot, 1);

        float hz = __shfl_down_sync(0xffffffffu, dot, 2);
        float hn = __shfl_down_sync(0xffffffffu, dot, 4);

        float r  = fmaf(tanh_f(0.5f*(xr + dot)), 0.5f, 0.5f);
        float z  = fmaf(tanh_f(0.5f*(xz + hz)),  0.5f, 0.5f);
        float uu = xn + r*hn;
        float nn = tanh_f(uu);
        float hv = (1.f - z)*nn + z*ho;
        if (store_lane) {
            h_s[cur ^ 1][u] = hv;
            y[(b*TT + tt)*DD + dir*HH + u] = hv;
        }
        __syncthreads();
    }
    if (tid < HH) hout[(hid_base + dir)*BB*HH + b*HH + tid] = h_s[0][tid];
}

// ---------------- layer-0 GRU: fused embedding gather + weight convert ------
__global__ __launch_bounds__(640) void gru0_fused(
    const int* __restrict__ x,
    const float* __restrict__ Wih0f, const float* __restrict__ Wih0b,
    const float* __restrict__ Whh0f, const float* __restrict__ Whh0b,
    const float* __restrict__ hidden,
    float* __restrict__ y, float* __restrict__ hout,
    const float* __restrict__ Wlin,
    const float* __restrict__ W1f, const float* __restrict__ W1b)
{
    const int tid = threadIdx.x;
    if (blockIdx.x >= 64) {
        const int cb = blockIdx.x - 64;              // 0..83
        const int stride = 84 * 640;
        for (int e4 = cb*640 + tid; e4 < W16_N4; e4 += stride) {
            const float* src;
            int off4;
            if (e4 < VV*KK/4)                 { src = Wlin; off4 = e4; }
            else if (e4 < (VV*KK + GG*KK)/4)  { src = W1f;  off4 = e4 - VV*KK/4; }
            else                              { src = W1b;  off4 = e4 - (VV*KK + GG*KK)/4; }
            float4 v = *reinterpret_cast<const float4*>(src + off4*4);
            __half2* o = reinterpret_cast<__half2*>(g_w16 + (size_t)e4*4);
            o[0] = __floats2half2_rn(v.x, v.y);
            o[1] = __floats2half2_rn(v.z, v.w);
        }
        return;
    }

    int dir = blockIdx.x >> 5;
    int b   = blockIdx.x & 31;
    const float* Wih = dir ? Wih0b : Wih0f;
    const float* Whh = dir ? Whh0b : Whh0f;

    __shared__ __align__(16) float h_s[2][104];
    __shared__ __align__(16) float gx_all[TT*GG + 8];
    __shared__ int tok_s[TT];

    if (tid < TT) tok_s[tid] = x[b*TT + tid];
    __syncthreads();

    for (int q = tid; q < TT*GG; q += 640) {
        int row = q / GG, gg = q - row*GG;
        gx_all[q] = Wih[(size_t)gg*VV + tok_s[row]];
    }

    gru_core(gx_all, h_s, Whh, hidden, 0, dir, b, y, hout, tid);
}

// ---------------- layer-1 GRU ----------------
__global__ __launch_bounds__(640) void gru1_kernel(
    const float* __restrict__ gxf, const float* __restrict__ gxb, int ldg_,
    const float* __restrict__ Whhf, const float* __restrict__ Whhb,
    const float* __restrict__ hidden,
    float* __restrict__ y, float* __restrict__ hout)
{
    int dir = blockIdx.x >> 5;
    int b   = blockIdx.x & 31;
    const float* gx  = dir ? gxb  : gxf;
    const float* Whh = dir ? Whhb : Whhf;
    const int tid = threadIdx.x;

    __shared__ __align__(16) float h_s[2][104];
    __shared__ __align__(16) float gx_all[TT*GG + 8];

    for (int q = tid; q < TT*(GG/2); q += 640) {
        int row = q / (GG/2);
        int c2  = q - row*(GG/2);
        *reinterpret_cast<float2*>(gx_all + row*GG + c2*2) =
            *reinterpret_cast<const float2*>(gx + (size_t)(b*TT + row)*ldg_ + c2*2);
    }

    gru_core(gx_all, h_s, Whh, hidden, 2, dir, b, y, hout, tid);
}

// ================= shared GEMM constants =====================================
#define KP   216
#define KC   13
#define A_BY 55296

// ================= projection GEMM: fp16 1-pass, cp.async, 1 tile/CTA ========
#define PJ_SMEM 110592    // A + B

__global__ __launch_bounds__(512, 1) void pj_gemm(
    const float* __restrict__ A, const __half* __restrict__ Bw,
    float* __restrict__ C)
{
    const int Ntot = 2*GG;   // 600
    extern __shared__ __align__(16) unsigned char dsm[];
    const uint32_t sb = smem_u32(dsm);
    const int tid = threadIdx.x;
    const int m0  = blockIdx.x * 128;
    const int n0  = blockIdx.y * 128;

    // zero K pads of both regions (A, B)
    for (int q = tid; q < 2*1024; q += 512) {
        int reg = q >> 10;
        int j   = q & 1023;
        int row = j >> 3, wd = j & 7;
        STS32(sb + (uint32_t)reg*A_BY + ((uint32_t)row*KP + 200)*2 + (uint32_t)wd*4, 0u);
    }

    // cp.async B tile (row-guarded)
    #pragma unroll
    for (int q = 0; q < 7; q++) {
        int u = tid + q*512;
        if (u < 3200) {
            int row = u / 25, ch = u % 25;
            int gr  = n0 + row;
            if (gr < Ntot)
                CP_ASYNC16(sb + A_BY + (uint32_t)row*(KP*2) + (uint32_t)ch*16,
                           (const void*)(Bw + (size_t)gr*KK + ch*8));
        }
    }
    CP_COMMIT();

    // load + convert A
    #pragma unroll
    for (int q = 0; q < 25; q++) {
        int u = tid + q*512;
        int row = u / 100, c2 = u % 100;
        float2 v = *reinterpret_cast<const float2*>(A + (size_t)(m0+row)*KK + c2*2);
        STS32(sb + ((uint32_t)row*KP + (uint32_t)c2*2)*2, cvt2_fp(v.x, v.y));
    }
    CP_WAIT0();
    __syncthreads();

    const int wid = tid >> 5, lane = tid & 31;
    const int wm = wid & 3, wn = wid >> 2;
    const int lr = lane & 7, lq = lane >> 3;
    const uint32_t aRow = (uint32_t)(wm*32 + (lq & 1)*8 + lr);
    const uint32_t aCol = (uint32_t)((lq >> 1)*8);
    const uint32_t bRow = (uint32_t)(wn*32 + (lq >> 1)*8 + lr);
    const uint32_t bCol = (uint32_t)((lq & 1)*8);
    const uint32_t aB = sb + (aRow*KP + aCol)*2;
    const uint32_t bB = sb + A_BY + (bRow*KP + bCol)*2;

    float acc[2][4][4];
    #pragma unroll
    for (int mt = 0; mt < 2; mt++)
        #pragma unroll
        for (int ns = 0; ns < 4; ns++)
            #pragma unroll
            for (int q = 0; q < 4; q++) acc[mt][ns][q] = 0.f;

    #pragma unroll
    for (int kc = 0; kc < KC; kc++) {
        const uint32_t kOff = (uint32_t)kc * 32;
        uint32_t ah[2][4], bh[2][4];
        #pragma unroll
        for (int mt = 0; mt < 2; mt++)
            ldsm4(ah[mt], aB + (uint32_t)(mt*16*KP)*2 + kOff);
        #pragma unroll
        for (int nb = 0; nb < 2; nb++)
            ldsm4(bh[nb], bB + (uint32_t)(nb*16*KP)*2 + kOff);
        #pragma unroll
        for (int mt = 0; mt < 2; mt++)
            #pragma unroll
            for (int ns = 0; ns < 4; ns++)
                mma_fp16(acc[mt][ns], ah[mt],
                         bh[ns>>1][(ns&1)*2], bh[ns>>1][(ns&1)*2+1]);
    }

    const int r0 = m0 + wm*32 + (lane >> 2);
    const int c0 = n0 + wn*32 + (lane & 3)*2;
    #pragma unroll
    for (int mt = 0; mt < 2; mt++)
        #pragma unroll
        for (int ns = 0; ns < 4; ns++) {
            int row = r0 + mt*16;
            int col = c0 + ns*8;
            if (col < Ntot) {
                *reinterpret_cast<float2*>(C + (size_t)row*Ntot + col) =
                    make_float2(acc[mt][ns][0], acc[mt][ns][1]);
                *reinterpret_cast<float2*>(C + (size_t)(row+8)*Ntot + col) =
                    make_float2(acc[mt][ns][2], acc[mt][ns][3]);
            }
        }
}

// ================= final GEMM: fp16, cp.async 3-stage, 128x128 tiles =========
// (Round-12 configuration: best measured — 16 warps, 1 CTA/SM, 3-stage.)
#define WG_SMEM 221184     // A + 3 B stages

__global__ __launch_bounds__(512, 1) void wl_gemm(
    const float* __restrict__ A, const __half* __restrict__ Bw,
    float* __restrict__ C)
{
    extern __shared__ __align__(16) unsigned char dsm[];
    const uint32_t sb = smem_u32(dsm);
    const int tid = threadIdx.x;
    const int m0  = blockIdx.x * 128;
    const int c   = blockIdx.y;
    const int S   = gridDim.y;
    const int ntn = VV / 128;          // 250

    for (int q = tid; q < 4*128*8; q += 512) {
        int reg = q >> 10;
        int j   = q & 1023;
        int row = j >> 3, wd = j & 7;
        STS32(sb + (uint32_t)reg*A_BY + ((uint32_t)row*KP + 200)*2 + (uint32_t)wd*4, 0u);
    }

    #pragma unroll
    for (int q = 0; q < 25; q++) {
        int u = tid + q*512;
        int row = u / 100, c2 = u % 100;
        float2 v = *reinterpret_cast<const float2*>(A + (size_t)(m0+row)*KK + c2*2);
        STS32(sb + ((uint32_t)row*KP + (uint32_t)c2*2)*2, cvt2_fp(v.x, v.y));
    }

    auto issue = [&](int tn, int st) {
        const int n0 = tn * 128;
        const uint32_t bs = sb + (uint32_t)(1 + st)*A_BY;
        #pragma unroll
        for (int q = 0; q < 7; q++) {
            int u = tid + q*512;
            if (u < 3200) {
                int row = u / 25, ch = u % 25;
                const __half* gp = Bw + (size_t)(n0 + row)*KK + ch*8;
                CP_ASYNC16(bs + (uint32_t)row*(KP*2) + (uint32_t)ch*16,
                           (const void*)gp);
            }
        }
    };

    {
        int t0 = c;
        if (t0 < ntn) issue(t0, 0);
        CP_COMMIT();
        int t1 = c + S;
        if (t1 < ntn) issue(t1, 1);
        CP_COMMIT();
    }

    const int wid = tid >> 5, lane = tid & 31;
    const int wm = wid & 3, wn = wid >> 2;
    const int lr = lane & 7, lq = lane >> 3;
    const uint32_t aRow = (uint32_t)(wm*32 + (lq & 1)*8 + lr);
    const uint32_t aCol = (uint32_t)((lq >> 1)*8);
    const uint32_t bRow = (uint32_t)(wn*32 + (lq >> 1)*8 + lr);
    const uint32_t bCol = (uint32_t)((lq & 1)*8);
    const uint32_t aB = sb + (aRow*KP + aCol)*2;
    uint32_t bB[3];
    #pragma unroll
    for (int s2 = 0; s2 < 3; s2++)
        bB[s2] = sb + (uint32_t)(1 + s2)*A_BY + (bRow*KP + bCol)*2;

    int phase = 0;
    for (int t = c; t < ntn; t += S, phase++) {
        const int slot = phase % 3;
        const int n0   = t * 128;

        CP_WAIT1();
        __syncthreads();

        const int tn = t + 2*S;
        if (tn < ntn) issue(tn, (phase + 2) % 3);
        CP_COMMIT();

        float acc[2][4][4];
        #pragma unroll
        for (int mt = 0; mt < 2; mt++)
            #pragma unroll
            for (int ns = 0; ns < 4; ns++)
                #pragma unroll
                for (int q = 0; q < 4; q++) acc[mt][ns][q] = 0.f;

        #pragma unroll
        for (int kc = 0; kc < KC; kc++) {
            const uint32_t kOff = (uint32_t)kc * 32;
            uint32_t ah[2][4], bh[2][4];
            #pragma unroll
            for (int mt = 0; mt < 2; mt++)
                ldsm4(ah[mt], aB + (uint32_t)(mt*16*KP)*2 + kOff);
            #pragma unroll
            for (int nb = 0; nb < 2; nb++)
                ldsm4(bh[nb], bB[slot] + (uint32_t)(nb*16*KP)*2 + kOff);
            #pragma unroll
            for (int mt = 0; mt < 2; mt++)
                #pragma unroll
                for (int ns = 0; ns < 4; ns++)
                    mma_fp16(acc[mt][ns], ah[mt], bh[ns>>1][(ns&1)*2], bh[ns>>1][(ns&1)*2+1]);
        }

        const int r0 = m0 + wm*32 + (lane >> 2);
        const int c0 = n0 + wn*32 + (lane & 3)*2;
        #pragma unroll
        for (int mt = 0; mt < 2; mt++)
            #pragma unroll
            for (int ns = 0; ns < 4; ns++) {
                int row = r0 + mt*16;
                int col = c0 + ns*8;
                *reinterpret_cast<float2*>(C + (size_t)row*VV + col) =
                    make_float2(acc[mt][ns][0], acc[mt][ns][1]);
                *reinterpret_cast<float2*>(C + (size_t)(row+8)*VV + col) =
                    make_float2(acc[mt][ns][2], acc[mt][ns][3]);
            }
    }
}

// ---------------- launch ----------------
extern "C" void kernel_launch(void* const* d_in, const int* in_sizes, int n_in,
                              void* d_out, int out_size) {
    const int*   x      = (const int*)  d_in[0];
    const float* hidden = (const float*)d_in[1];
    const float* Wih0f  = (const float*)d_in[2];
    const float* Whh0f  = (const float*)d_in[3];
    const float* Wih0b  = (const float*)d_in[4];
    const float* Whh0b  = (const float*)d_in[5];
    const float* Wih1f  = (const float*)d_in[6];
    const float* Whh1f  = (const float*)d_in[7];
    const float* Wih1b  = (const float*)d_in[8];
    const float* Whh1b  = (const float*)d_in[9];
    const float* Wlin   = (const float*)d_in[10];

    float* out  = (float*)d_out;
    float* hout = out + (out_size - 4*BB*HH);

    void *p_y0, *p_gx1, *p_y1, *p_w16;
    cudaGetSymbolAddress(&p_y0,   g_y0);
    cudaGetSymbolAddress(&p_gx1,  g_gx1);
    cudaGetSymbolAddress(&p_y1,   g_y1);
    cudaGetSymbolAddress(&p_w16,  g_w16);
    __half* w16 = (__half*)p_w16;

    cudaFuncSetAttribute(pj_gemm, cudaFuncAttributeMaxDynamicSharedMemorySize, PJ_SMEM);
    cudaFuncSetAttribute(wl_gemm, cudaFuncAttributeMaxDynamicSharedMemorySize, WG_SMEM);

    // 1. GRU layer 0 (fused gather + fp16 converts on idle SMs)
    gru0_fused<<<148, 640>>>(x, Wih0f, Wih0b, Whh0f, Whh0b, hidden,
                             (float*)p_y0, hout, Wlin, Wih1f, Wih1b);

    // 2. fused layer-1 projections (fp16 1-pass, grid 5x5)
    pj_gemm<<<dim3(5, 5), 512, PJ_SMEM>>>((const float*)p_y0,
                                          w16 + W1F_OFF, (float*)p_gx1);

    // 3. GRU layer 1
    gru1_kernel<<<64, 640>>>((const float*)p_gx1, (const float*)p_gx1 + GG,
                             2*GG, Whh1f, Whh1b, hidden,
                             (float*)p_y1, hout);

    // 4. final projection: fp16 cp.async 3-stage, grid 5x29 (round-12 config)
    wl_gemm<<<dim3(5, 29), 512, WG_SMEM>>>((const float*)p_y1,
                                           w16 + WL_OFF, out);
}